// round 1
// baseline (speedup 1.0000x reference)
#include <cuda_runtime.h>

// Problem constants
#define NB     2
#define CIN    256
#define NTOK   4096
#define NH     8
#define DH     64
#define CINNER 512         // NH*DH
#define CQKV   1536        // 3*CINNER

// Scratch (allocation-free rule: __device__ globals)
__device__ float g_qkv[NB * CQKV * NTOK];            // [B][1536][N]  q:0-511 k:512-1023 v:1024-1535
__device__ float g_norms[2 * NB * NH * NTOK];        // q2 then k2
__device__ float g_ao[NB * CINNER * NTOK];           // attention output [B][512][N]

// ---------------------------------------------------------------------------
// Generic tiled GEMM: Y[b][o][n] = sum_c A[o][c] * X[b][c][n]
// Block: 64(o) x 64(n) tile, 256 threads, 4x4 micro-tiles, kTile=16.
// ---------------------------------------------------------------------------
__global__ void __launch_bounds__(256) gemm_kernel(
    const float* __restrict__ A,   // [M][K]
    const float* __restrict__ X,   // [B][K][NTOK]
    float*       __restrict__ Y,   // [B][M][NTOK]
    int K, long xBatchStride, long yBatchStride)
{
    __shared__ float Wt[16][68];   // [kk][o], pad 68 keeps 16B alignment + bank spread
    __shared__ float Xs[16][64];   // [kk][n]

    const int tid = threadIdx.x;
    const int tx = tid & 15, ty = tid >> 4;
    const int n0 = blockIdx.x * 64;
    const int o0 = blockIdx.y * 64;
    const float* Xb = X + (long)blockIdx.z * xBatchStride;
    float*       Yb = Y + (long)blockIdx.z * yBatchStride;

    float acc[4][4];
    #pragma unroll
    for (int a = 0; a < 4; a++)
        #pragma unroll
        for (int b = 0; b < 4; b++) acc[a][b] = 0.f;

    for (int kc = 0; kc < K; kc += 16) {
        __syncthreads();
        #pragma unroll
        for (int l = tid; l < 16 * 64; l += 256) {
            int kk = l & 15, oo = l >> 4;
            Wt[kk][oo] = A[(long)(o0 + oo) * K + kc + kk];
        }
        #pragma unroll
        for (int l = tid; l < 16 * 64; l += 256) {
            int nn = l & 63, kk = l >> 6;
            Xs[kk][nn] = Xb[(long)(kc + kk) * NTOK + n0 + nn];
        }
        __syncthreads();
        #pragma unroll
        for (int kk = 0; kk < 16; kk++) {
            float4 wv = *(const float4*)&Wt[kk][4 * ty];
            float4 xv = *(const float4*)&Xs[kk][4 * tx];
            float w[4] = {wv.x, wv.y, wv.z, wv.w};
            float x[4] = {xv.x, xv.y, xv.z, xv.w};
            #pragma unroll
            for (int a = 0; a < 4; a++)
                #pragma unroll
                for (int b = 0; b < 4; b++)
                    acc[a][b] = fmaf(w[a], x[b], acc[a][b]);
        }
    }
    #pragma unroll
    for (int a = 0; a < 4; a++) {
        float4 v = make_float4(acc[a][0], acc[a][1], acc[a][2], acc[a][3]);
        *(float4*)&Yb[(long)(o0 + 4 * ty + a) * NTOK + n0 + 4 * tx] = v;
    }
}

// ---------------------------------------------------------------------------
// Norms: q2[b][h][n], k2[b][h][n] from g_qkv
// ---------------------------------------------------------------------------
__global__ void __launch_bounds__(256) norms_kernel()
{
    int idx = blockIdx.x * 256 + threadIdx.x;   // total NB*NH*2*NTOK = 131072
    int n = idx & (NTOK - 1);
    int t = idx >> 12;          // 0..31
    int h = t & 7;
    int pb = t >> 3;            // 0..3
    int part = pb & 1;          // 0=q, 1=k
    int b = pb >> 1;
    const float* p = g_qkv + ((long)(b * CQKV + part * CINNER + h * DH)) * NTOK + n;
    float s = 0.f;
    #pragma unroll
    for (int d = 0; d < DH; d++) { float v = p[(long)d * NTOK]; s = fmaf(v, v, s); }
    g_norms[(long)part * (NB * NH * NTOK) + (long)(b * NH + h) * NTOK + n] = s;
}

// ---------------------------------------------------------------------------
// Flash-style distance attention, fp32.
// Block = 256 threads, handles one (b,h) and 64 queries; loops 64-key tiles.
// Thread (ty,tx): rows i = 4ty+a, key cols j = 4tx+bb, out cols dd = 4tx+bb.
// ---------------------------------------------------------------------------
__global__ void __launch_bounds__(256, 2) attn_kernel()
{
    extern __shared__ float sm[];
    float* Qt  = sm;            // [d][i]   64x64
    float* Kt  = sm + 4096;     // [d][j]   64x64
    float* Vs  = sm + 8192;     // [j][dd^swz(j)] 64x64
    float* Ps  = sm + 12288;    // [i][j]   64x64
    float* q2s = sm + 16384;    // [64]
    float* k2s = sm + 16448;    // [64]

    const int tid = threadIdx.x;
    const int tx = tid & 15, ty = tid >> 4;
    const int qt = blockIdx.x, h = blockIdx.y, b = blockIdx.z;
    const int n0 = qt * 64;
    const int bh = b * NH + h;

    const float* qb = g_qkv + ((long)(b * CQKV + h * DH)) * NTOK;
    const float* kb = g_qkv + ((long)(b * CQKV + CINNER + h * DH)) * NTOK;
    const float* vb = g_qkv + ((long)(b * CQKV + 2 * CINNER + h * DH)) * NTOK;
    const float* q2g = g_norms + (long)bh * NTOK;
    const float* k2g = g_norms + (long)NB * NH * NTOK + (long)bh * NTOK;

    #pragma unroll
    for (int l = tid; l < 4096; l += 256) {
        int d = l >> 6, i = l & 63;
        Qt[d * 64 + i] = qb[(long)d * NTOK + n0 + i];
    }
    if (tid < 64) q2s[tid] = q2g[n0 + tid];

    float m[4], lsum[4], o[4][4];   // o[bb][a]: out(i=4ty+a, dd=4tx+bb)
    #pragma unroll
    for (int a = 0; a < 4; a++) {
        m[a] = -1e30f; lsum[a] = 0.f;
        #pragma unroll
        for (int bb = 0; bb < 4; bb++) o[bb][a] = 0.f;
    }

    for (int kt = 0; kt < NTOK / 64; kt++) {
        const int nk = kt * 64;
        __syncthreads();   // protect prior tile's smem reads (and Q load, first iter)
        #pragma unroll
        for (int l = tid; l < 4096; l += 256) {
            int d = l >> 6, j = l & 63;
            Kt[d * 64 + j] = kb[(long)d * NTOK + nk + j];
        }
        #pragma unroll
        for (int l = tid; l < 4096; l += 256) {
            int dd = l >> 6, j = l & 63;
            Vs[j * 64 + (dd ^ ((j & 15) << 2))] = vb[(long)dd * NTOK + nk + j];
        }
        if (tid < 64) k2s[tid] = k2g[nk + tid];
        __syncthreads();

        // ---- QK^T (64 x 64 tile) ----
        float s[4][4];
        #pragma unroll
        for (int a = 0; a < 4; a++)
            #pragma unroll
            for (int bb = 0; bb < 4; bb++) s[a][bb] = 0.f;

        #pragma unroll 8
        for (int kk = 0; kk < 64; kk++) {
            float4 qv = *(const float4*)&Qt[kk * 64 + 4 * ty];
            float4 kv = *(const float4*)&Kt[kk * 64 + 4 * tx];
            float qq[4] = {qv.x, qv.y, qv.z, qv.w};
            float kr[4] = {kv.x, kv.y, kv.z, kv.w};
            #pragma unroll
            for (int a = 0; a < 4; a++)
                #pragma unroll
                for (int bb = 0; bb < 4; bb++)
                    s[a][bb] = fmaf(qq[a], kr[bb], s[a][bb]);
        }

        // ---- distance + online softmax ----
        float k2c[4] = {k2s[4 * tx], k2s[4 * tx + 1], k2s[4 * tx + 2], k2s[4 * tx + 3]};
        #pragma unroll
        for (int a = 0; a < 4; a++) {
            float q2v = q2s[4 * ty + a];
            float rmax = -1e30f;
            #pragma unroll
            for (int bb = 0; bb < 4; bb++) {
                float d2  = q2v + k2c[bb] - 2.f * s[a][bb];
                float sim = sqrtf(fmaxf(d2, 0.f));
                s[a][bb] = sim;
                rmax = fmaxf(rmax, sim);
            }
            #pragma unroll
            for (int off = 8; off; off >>= 1)
                rmax = fmaxf(rmax, __shfl_xor_sync(0xffffffffu, rmax, off, 16));
            float mn   = fmaxf(m[a], rmax);
            float corr = __expf(m[a] - mn);
            m[a] = mn;
            float ps = 0.f;
            #pragma unroll
            for (int bb = 0; bb < 4; bb++) {
                float p = __expf(s[a][bb] - mn);
                s[a][bb] = p;
                ps += p;
            }
            #pragma unroll
            for (int off = 8; off; off >>= 1)
                ps += __shfl_xor_sync(0xffffffffu, ps, off, 16);
            lsum[a] = lsum[a] * corr + ps;
            #pragma unroll
            for (int bb = 0; bb < 4; bb++) o[bb][a] *= corr;
            *(float4*)&Ps[(4 * ty + a) * 64 + 4 * tx] =
                make_float4(s[a][0], s[a][1], s[a][2], s[a][3]);
        }
        __syncthreads();

        // ---- P @ V ----
        #pragma unroll 4
        for (int j = 0; j < 64; j++) {
            float4 vv = *(const float4*)&Vs[j * 64 + ((4 * tx) ^ ((j & 15) << 2))];
            float vr[4] = {vv.x, vv.y, vv.z, vv.w};
            float pr[4];
            #pragma unroll
            for (int a = 0; a < 4; a++) pr[a] = Ps[(4 * ty + a) * 64 + j];
            #pragma unroll
            for (int bb = 0; bb < 4; bb++)
                #pragma unroll
                for (int a = 0; a < 4; a++)
                    o[bb][a] = fmaf(pr[a], vr[bb], o[bb][a]);
        }
    }

    // epilogue: normalize, write ao[b][h*64+dd][n0+i] (float4 along i)
    #pragma unroll
    for (int a = 0; a < 4; a++) {
        float inv = 1.f / lsum[a];
        #pragma unroll
        for (int bb = 0; bb < 4; bb++) o[bb][a] *= inv;
    }
    float* aob = g_ao + ((long)(b * CINNER + h * DH)) * NTOK;
    #pragma unroll
    for (int bb = 0; bb < 4; bb++) {
        float4 v = make_float4(o[bb][0], o[bb][1], o[bb][2], o[bb][3]);
        *(float4*)&aob[(long)(4 * tx + bb) * NTOK + n0 + 4 * ty] = v;
    }
}

// ---------------------------------------------------------------------------
extern "C" void kernel_launch(void* const* d_in, const int* in_sizes, int n_in,
                              void* d_out, int out_size)
{
    (void)in_sizes; (void)n_in; (void)out_size;
    const float* fmap  = (const float*)d_in[0];   // [2,256,64,64]
    const float* w_qkv = (const float*)d_in[1];   // [1536,256]
    const float* w_out = (const float*)d_in[2];   // [256,512]
    float* out = (float*)d_out;                   // [2,256,64,64]

    void* qkvPtr = nullptr;
    void* aoPtr  = nullptr;
    cudaGetSymbolAddress(&qkvPtr, g_qkv);
    cudaGetSymbolAddress(&aoPtr,  g_ao);

    // K1: QKV projection  [1536,256] @ [2,256,4096] -> g_qkv
    {
        dim3 grid(NTOK / 64, CQKV / 64, NB);
        gemm_kernel<<<grid, 256>>>(w_qkv, fmap, (float*)qkvPtr,
                                   CIN, (long)CIN * NTOK, (long)CQKV * NTOK);
    }
    // K2: norms
    norms_kernel<<<(NB * NH * 2 * NTOK) / 256, 256>>>();

    // K3: attention
    {
        const int smemBytes = (4 * 4096 + 128) * (int)sizeof(float);  // 66048
        cudaFuncSetAttribute(attn_kernel,
                             cudaFuncAttributeMaxDynamicSharedMemorySize, smemBytes);
        dim3 grid(NTOK / 64, NH, NB);
        attn_kernel<<<grid, 256, smemBytes>>>();
    }
    // K4: output projection [256,512] @ [2,512,4096] -> out
    {
        dim3 grid(NTOK / 64, CIN / 64, NB);
        gemm_kernel<<<grid, 256>>>(w_out, (const float*)aoPtr, out,
                                   CINNER, (long)CINNER * NTOK, (long)CIN * NTOK);
    }
}

// round 3
// speedup vs baseline: 2.7596x; 2.7596x over previous
#include <cuda_runtime.h>
#include <cstdint>

// Problem constants
#define NB     2
#define CIN    256
#define NTOK   4096
#define NH     8
#define DH     64
#define CINNER 512         // NH*DH
#define CQKV   1536        // 3*CINNER

// Scratch (allocation-free rule: __device__ globals)
__device__ float g_qkv[NB * CQKV * NTOK];            // [B][1536][N]
__device__ float g_norms[2 * NB * NH * NTOK];        // q2 then k2
__device__ float g_ao[NB * CINNER * NTOK];           // attention output [B][512][N]

// ---------------------------------------------------------------------------
// mma.sync tf32 helpers (sm_80 feature set -> works on base sm_103 target)
// ---------------------------------------------------------------------------
__device__ __forceinline__ uint32_t tf32r(float f) {
    uint32_t u;
    asm("cvt.rna.tf32.f32 %0, %1;" : "=r"(u) : "f"(f));
    return u;
}

__device__ __forceinline__ void mma8(float c[4], const uint32_t a[4],
                                     uint32_t b0, uint32_t b1) {
    asm volatile(
        "mma.sync.aligned.m16n8k8.row.col.f32.tf32.tf32.f32 "
        "{%0,%1,%2,%3}, {%4,%5,%6,%7}, {%8,%9}, {%0,%1,%2,%3};"
        : "+f"(c[0]), "+f"(c[1]), "+f"(c[2]), "+f"(c[3])
        : "r"(a[0]), "r"(a[1]), "r"(a[2]), "r"(a[3]), "r"(b0), "r"(b1));
}

// ---------------------------------------------------------------------------
// Generic tiled GEMM: Y[b][o][n] = sum_c A[o][c] * X[b][c][n] (fp32 SIMT)
// ---------------------------------------------------------------------------
__global__ void __launch_bounds__(256) gemm_kernel(
    const float* __restrict__ A, const float* __restrict__ X, float* __restrict__ Y,
    int K, long xBatchStride, long yBatchStride)
{
    __shared__ float Wt[16][68];
    __shared__ float Xs[16][64];

    const int tid = threadIdx.x;
    const int tx = tid & 15, ty = tid >> 4;
    const int n0 = blockIdx.x * 64;
    const int o0 = blockIdx.y * 64;
    const float* Xb = X + (long)blockIdx.z * xBatchStride;
    float*       Yb = Y + (long)blockIdx.z * yBatchStride;

    float acc[4][4];
    #pragma unroll
    for (int a = 0; a < 4; a++)
        #pragma unroll
        for (int b = 0; b < 4; b++) acc[a][b] = 0.f;

    for (int kc = 0; kc < K; kc += 16) {
        __syncthreads();
        #pragma unroll
        for (int l = tid; l < 16 * 64; l += 256) {
            int kk = l & 15, oo = l >> 4;
            Wt[kk][oo] = A[(long)(o0 + oo) * K + kc + kk];
        }
        #pragma unroll
        for (int l = tid; l < 16 * 64; l += 256) {
            int nn = l & 63, kk = l >> 6;
            Xs[kk][nn] = Xb[(long)(kc + kk) * NTOK + n0 + nn];
        }
        __syncthreads();
        #pragma unroll
        for (int kk = 0; kk < 16; kk++) {
            float4 wv = *(const float4*)&Wt[kk][4 * ty];
            float4 xv = *(const float4*)&Xs[kk][4 * tx];
            float w[4] = {wv.x, wv.y, wv.z, wv.w};
            float x[4] = {xv.x, xv.y, xv.z, xv.w};
            #pragma unroll
            for (int a = 0; a < 4; a++)
                #pragma unroll
                for (int b = 0; b < 4; b++)
                    acc[a][b] = fmaf(w[a], x[b], acc[a][b]);
        }
    }
    #pragma unroll
    for (int a = 0; a < 4; a++) {
        float4 v = make_float4(acc[a][0], acc[a][1], acc[a][2], acc[a][3]);
        *(float4*)&Yb[(long)(o0 + 4 * ty + a) * NTOK + n0 + 4 * tx] = v;
    }
}

// ---------------------------------------------------------------------------
// Norms: q2[b][h][n], k2[b][h][n]
// ---------------------------------------------------------------------------
__global__ void __launch_bounds__(256) norms_kernel()
{
    int idx = blockIdx.x * 256 + threadIdx.x;
    int n = idx & (NTOK - 1);
    int t = idx >> 12;
    int h = t & 7;
    int pb = t >> 3;
    int part = pb & 1;
    int b = pb >> 1;
    const float* p = g_qkv + ((long)(b * CQKV + part * CINNER + h * DH)) * NTOK + n;
    float s = 0.f;
    #pragma unroll
    for (int d = 0; d < DH; d++) { float v = p[(long)d * NTOK]; s = fmaf(v, v, s); }
    g_norms[(long)part * (NB * NH * NTOK) + (long)(b * NH + h) * NTOK + n] = s;
}

// ---------------------------------------------------------------------------
// Flash distance attention via mma.sync tf32.
// CTA = 256 threads = 8 warps; each warp owns 16 query rows (128 q / CTA).
// Fixed-shift softmax (scores bounded) -> no running max, no rescale.
// K/V staged in smem in exact mma B-fragment order:
//   K slot(j,d)  = (j>>3)*516 + (d>>3)*64 + ((j&7)*4+(d&3))*2 + ((d>>2)&1)
//   V slot(j,dd) = (dd>>3)*544 + (j>>3)*68 + ((dd&7)*4+(j&3))*2 + ((j>>2)&1)
// ---------------------------------------------------------------------------
__global__ void __launch_bounds__(256, 2) attn_mma_kernel()
{
    __shared__ uint32_t KF[8 * 516];   // 4128
    __shared__ uint32_t VF[8 * 544];   // 4352
    __shared__ float    k2s[64];

    const int tid  = threadIdx.x;
    const int wid  = tid >> 5;
    const int lane = tid & 31;
    const int quad = lane & 3;
    const int g    = lane >> 2;
    const int n0   = blockIdx.x * 128;
    const int h = blockIdx.y, b = blockIdx.z;
    const int bh = b * NH + h;

    const float* qb  = g_qkv + (long)(b * CQKV + h * DH) * NTOK;
    const float* kb  = g_qkv + (long)(b * CQKV + CINNER + h * DH) * NTOK;
    const float* vb  = g_qkv + (long)(b * CQKV + 2 * CINNER + h * DH) * NTOK;
    const float* k2g = g_norms + (long)NB * NH * NTOK + (long)bh * NTOK;

    const int i0 = n0 + wid * 16 + g;      // this thread's query row (and +8)

    // Q A-fragments, kept in registers for the whole kernel (tf32-rounded)
    uint32_t aq[8][4];
    #pragma unroll
    for (int ks = 0; ks < 8; ks++) {
        int d = quad + 8 * ks;
        aq[ks][0] = tf32r(qb[(long)d * NTOK + i0]);
        aq[ks][1] = tf32r(qb[(long)d * NTOK + i0 + 8]);
        aq[ks][2] = tf32r(qb[(long)(d + 4) * NTOK + i0]);
        aq[ks][3] = tf32r(qb[(long)(d + 4) * NTOK + i0 + 8]);
    }
    const float q2a = g_norms[(long)bh * NTOK + i0];
    const float q2b = g_norms[(long)bh * NTOK + i0 + 8];

    constexpr float LOG2E  = 1.4426950408889634f;
    constexpr float NSHIFT = -12.0f * LOG2E;   // fixed shift of 12 in the exponent

    float o[8][4];
    #pragma unroll
    for (int nt = 0; nt < 8; nt++)
        #pragma unroll
        for (int r = 0; r < 4; r++) o[nt][r] = 0.f;
    float lsum0 = 0.f, lsum1 = 0.f;

    const int srcA = (lane & ~3) | (quad >> 1);
    const int srcB = srcA + 2;

    for (int kt = 0; kt < NTOK / 64; kt++) {
        const int nk = kt * 64;
        __syncthreads();   // previous iteration done reading KF/VF/k2s

        // ---- stage K tile (64 keys x 64 d) into fragment order ----
        #pragma unroll
        for (int it = 0; it < 4; it++) {
            int idx = tid + it * 256;            // 0..1023
            int d = idx >> 4, j4 = (idx & 15) << 2;
            float4 kv = *(const float4*)(kb + (long)d * NTOK + nk + j4);
            int base = (d >> 3) * 64 + (d & 3) * 2 + ((d >> 2) & 1);
            float v4[4] = {kv.x, kv.y, kv.z, kv.w};
            #pragma unroll
            for (int r = 0; r < 4; r++) {
                int j = j4 + r;
                KF[(j >> 3) * 516 + base + (j & 7) * 8] = tf32r(v4[r]);
            }
        }
        // ---- stage V tile (64 keys x 64 dd) into fragment order ----
        #pragma unroll
        for (int it = 0; it < 4; it++) {
            int idx = tid + it * 256;
            int dd = idx >> 4, j4 = (idx & 15) << 2;
            float4 vv = *(const float4*)(vb + (long)dd * NTOK + nk + j4);
            int base = (dd >> 3) * 544 + (dd & 7) * 8;
            float v4[4] = {vv.x, vv.y, vv.z, vv.w};
            #pragma unroll
            for (int r = 0; r < 4; r++) {
                int j = j4 + r;
                VF[base + (j >> 3) * 68 + (j & 3) * 2 + ((j >> 2) & 1)] = tf32r(v4[r]);
            }
        }
        if (tid < 64) k2s[tid] = k2g[nk + tid];
        __syncthreads();

        // ---- compute: stream 8-key blocks (nt) ----
        #pragma unroll
        for (int nt = 0; nt < 8; nt++) {
            // QK^T for this 16x8 block
            float c[4] = {0.f, 0.f, 0.f, 0.f};
            const uint32_t* kfp = KF + nt * 516 + lane * 2;
            #pragma unroll
            for (int ks = 0; ks < 8; ks++) {
                uint2 bb = *(const uint2*)(kfp + ks * 64);
                mma8(c, aq[ks], bb.x, bb.y);
            }
            // distance + exp (fixed shift)
            float k2c0 = k2s[8 * nt + 2 * quad];
            float k2c1 = k2s[8 * nt + 2 * quad + 1];
            float p[4];
            {
                float d2, s;
                d2 = fmaxf(q2a + k2c0 - 2.f * c[0], 0.f);
                asm("sqrt.approx.f32 %0, %1;" : "=f"(s) : "f"(d2));
                asm("ex2.approx.f32 %0, %1;" : "=f"(p[0]) : "f"(fmaf(s, LOG2E, NSHIFT)));
                d2 = fmaxf(q2a + k2c1 - 2.f * c[1], 0.f);
                asm("sqrt.approx.f32 %0, %1;" : "=f"(s) : "f"(d2));
                asm("ex2.approx.f32 %0, %1;" : "=f"(p[1]) : "f"(fmaf(s, LOG2E, NSHIFT)));
                d2 = fmaxf(q2b + k2c0 - 2.f * c[2], 0.f);
                asm("sqrt.approx.f32 %0, %1;" : "=f"(s) : "f"(d2));
                asm("ex2.approx.f32 %0, %1;" : "=f"(p[2]) : "f"(fmaf(s, LOG2E, NSHIFT)));
                d2 = fmaxf(q2b + k2c1 - 2.f * c[3], 0.f);
                asm("sqrt.approx.f32 %0, %1;" : "=f"(s) : "f"(d2));
                asm("ex2.approx.f32 %0, %1;" : "=f"(p[3]) : "f"(fmaf(s, LOG2E, NSHIFT)));
            }
            lsum0 += p[0] + p[1];
            lsum1 += p[2] + p[3];

            // C-frag -> A-frag transpose via quad shuffles (tf32-rounded)
            uint32_t up0 = tf32r(p[0]), up1 = tf32r(p[1]);
            uint32_t up2 = tf32r(p[2]), up3 = tf32r(p[3]);
            uint32_t x0 = __shfl_sync(0xffffffffu, up0, srcA);
            uint32_t x1 = __shfl_sync(0xffffffffu, up1, srcA);
            uint32_t x2 = __shfl_sync(0xffffffffu, up2, srcA);
            uint32_t x3 = __shfl_sync(0xffffffffu, up3, srcA);
            uint32_t y0 = __shfl_sync(0xffffffffu, up0, srcB);
            uint32_t y1 = __shfl_sync(0xffffffffu, up1, srcB);
            uint32_t y2 = __shfl_sync(0xffffffffu, up2, srcB);
            uint32_t y3 = __shfl_sync(0xffffffffu, up3, srcB);
            uint32_t ap[4];
            ap[0] = (quad & 1) ? x1 : x0;
            ap[1] = (quad & 1) ? x3 : x2;
            ap[2] = (quad & 1) ? y1 : y0;
            ap[3] = (quad & 1) ? y3 : y2;

            // PV: O[.,ddnt] += P(:,8nt..8nt+7) @ V(8nt..8nt+7, ddnt)
            const uint32_t* vfp = VF + nt * 68 + lane * 2;
            #pragma unroll
            for (int ddnt = 0; ddnt < 8; ddnt++) {
                uint2 vv = *(const uint2*)(vfp + ddnt * 544);
                mma8(o[ddnt], ap, vv.x, vv.y);
            }
        }
    }

    // ---- epilogue ----
    lsum0 += __shfl_xor_sync(0xffffffffu, lsum0, 1);
    lsum0 += __shfl_xor_sync(0xffffffffu, lsum0, 2);
    lsum1 += __shfl_xor_sync(0xffffffffu, lsum1, 1);
    lsum1 += __shfl_xor_sync(0xffffffffu, lsum1, 2);
    const float inv0 = 1.f / lsum0;
    const float inv1 = 1.f / lsum1;

    float* aob = g_ao + (long)(b * CINNER + h * DH) * NTOK;
    #pragma unroll
    for (int nt = 0; nt < 8; nt++) {
        int dd = 8 * nt + 2 * quad;
        aob[(long)dd * NTOK + i0]           = o[nt][0] * inv0;
        aob[(long)(dd + 1) * NTOK + i0]     = o[nt][1] * inv0;
        aob[(long)dd * NTOK + i0 + 8]       = o[nt][2] * inv1;
        aob[(long)(dd + 1) * NTOK + i0 + 8] = o[nt][3] * inv1;
    }
}

// ---------------------------------------------------------------------------
extern "C" void kernel_launch(void* const* d_in, const int* in_sizes, int n_in,
                              void* d_out, int out_size)
{
    (void)in_sizes; (void)n_in; (void)out_size;
    const float* fmap  = (const float*)d_in[0];   // [2,256,64,64]
    const float* w_qkv = (const float*)d_in[1];   // [1536,256]
    const float* w_out = (const float*)d_in[2];   // [256,512]
    float* out = (float*)d_out;                   // [2,256,64,64]

    void* qkvPtr = nullptr;
    void* aoPtr  = nullptr;
    cudaGetSymbolAddress(&qkvPtr, g_qkv);
    cudaGetSymbolAddress(&aoPtr,  g_ao);

    // K1: QKV projection  [1536,256] @ [2,256,4096] -> g_qkv
    {
        dim3 grid(NTOK / 64, CQKV / 64, NB);
        gemm_kernel<<<grid, 256>>>(w_qkv, fmap, (float*)qkvPtr,
                                   CIN, (long)CIN * NTOK, (long)CQKV * NTOK);
    }
    // K2: norms
    norms_kernel<<<(NB * NH * 2 * NTOK) / 256, 256>>>();

    // K3: tensor-core (mma.sync tf32) attention
    {
        dim3 grid(NTOK / 128, NH, NB);
        attn_mma_kernel<<<grid, 256>>>();
    }
    // K4: output projection [256,512] @ [2,512,4096] -> out
    {
        dim3 grid(NTOK / 64, CIN / 64, NB);
        gemm_kernel<<<grid, 256>>>(w_out, (const float*)aoPtr, out,
                                   CINNER, (long)CINNER * NTOK, (long)CIN * NTOK);
    }
}